// round 12
// baseline (speedup 1.0000x reference)
#include <cuda_runtime.h>
#include <cuda_fp16.h>
#include <cstdint>
#include <cstddef>

#define NN 100000
#define HH 512
#define EE 160000
#define BN_EPS 1e-5f
#define SLOPE 0.01f
#define NB_SCAN 391          // ceil(NN/256)

// ---------------- scratch ----------------
__device__ float  g_C[(size_t)NN * HH];     // fp32 node state (agg output)
__device__ __half g_Ah[(size_t)NN * HH];    // fp16 GEMM input
__device__ __half g_B16[(size_t)NN * HH];   // fp16 GEMM output (feeds gather)
__device__ float g_dinv[NN];
__device__ int   g_deg[NN];
__device__ int   g_off[NN + 1];
__device__ int   g_cur[NN];
__device__ int   g_part[NB_SCAN];
__device__ int   g_csrc[EE];
__device__ float g_cw[EE];
__device__ float g_colsum[HH];
__device__ float g_colsq[HH];
__device__ float g_scale[HH];
__device__ float g_shift[HH];
__device__ float g_weff[HH + 1];
__device__ int   g_is64;

// transposed fp16 weights: T[n][k] = fp16(W[k][n])
__device__ __half g_w1h[HH * HH];
__device__ __half g_wch[HH * HH];

// ---------------- helpers ----------------
__device__ __forceinline__ uint32_t smem_u32(const void* p) {
    uint32_t a;
    asm("{ .reg .u64 t; cvta.to.shared.u64 t, %1; cvt.u32.u64 %0, t; }"
        : "=r"(a) : "l"(p));
    return a;
}
__device__ __forceinline__ void ldsm_x4(uint32_t* r, uint32_t addr) {
    asm volatile("ldmatrix.sync.aligned.m8n8.x4.shared.b16 {%0,%1,%2,%3}, [%4];"
                 : "=r"(r[0]), "=r"(r[1]), "=r"(r[2]), "=r"(r[3]) : "r"(addr));
}
__device__ __forceinline__ void mma_f16(float* d, const uint32_t* a,
                                        const uint32_t* b) {
    asm volatile(
        "mma.sync.aligned.m16n8k16.row.col.f32.f16.f16.f32 "
        "{%0,%1,%2,%3}, {%4,%5,%6,%7}, {%8,%9}, {%0,%1,%2,%3};"
        : "+f"(d[0]), "+f"(d[1]), "+f"(d[2]), "+f"(d[3])
        : "r"(a[0]), "r"(a[1]), "r"(a[2]), "r"(a[3]), "r"(b[0]), "r"(b[1]));
}
__device__ __forceinline__ void cp16(uint32_t dst, const void* src) {
    asm volatile("cp.async.cg.shared.global [%0], [%1], 16;"
                 :: "r"(dst), "l"(src));
}
__device__ __forceinline__ float lrelu1(float x) {
    return x >= 0.f ? x : SLOPE * x;
}
__device__ __forceinline__ float4 xform(float4 v, int col,
                                        const float* __restrict__ scale,
                                        const float* __restrict__ shift) {
    float4 s = __ldg((const float4*)(scale + col));
    float4 t = __ldg((const float4*)(shift + col));
    v.x = lrelu1(fmaf(s.x, v.x, t.x));
    v.y = lrelu1(fmaf(s.y, v.y, t.y));
    v.z = lrelu1(fmaf(s.z, v.z, t.z));
    v.w = lrelu1(fmaf(s.w, v.w, t.w));
    return v;
}
__device__ __forceinline__ uint32_t packh(__half a, __half b) {
    return ((uint32_t)__half_as_ushort(a)) |
           ((uint32_t)__half_as_ushort(b) << 16);
}
// accumulate 16 halves (2x uint4) scaled by w into acc[16]
__device__ __forceinline__ void accum16(float* acc, const uint4* p, float w) {
    uint4 u0 = __ldg(p), u1 = __ldg(p + 1);
    uint32_t ua[8] = {u0.x, u0.y, u0.z, u0.w, u1.x, u1.y, u1.z, u1.w};
#pragma unroll
    for (int j = 0; j < 8; j++) {
        float2 f = __half22float2(*(__half2*)&ua[j]);
        acc[2 * j + 0] = fmaf(w, f.x, acc[2 * j + 0]);
        acc[2 * j + 1] = fmaf(w, f.y, acc[2 * j + 1]);
    }
}

// ---------------- setup ----------------
__global__ void k_prep(const int* __restrict__ ei) {
    int i = blockIdx.x * blockDim.x + threadIdx.x;
    if (i == 0)
        g_is64 = ((ei[1] | ei[3] | ei[5] | ei[7] | ei[9]) == 0) ? 1 : 0;
    if (i < NN) g_deg[i] = 0;
}
__global__ void k_deg(const int* __restrict__ ei) {
    int e = blockIdx.x * blockDim.x + threadIdx.x;
    if (e >= EE) return;
    int is64 = g_is64;
    int dst = is64 ? ei[2 * EE + 2 * e] : ei[EE + e];
    atomicAdd(&g_deg[dst], 1);
}
__global__ void k_dinv() {
    int i = blockIdx.x * blockDim.x + threadIdx.x;
    if (i < NN) g_dinv[i] = rsqrtf((float)g_deg[i] + 1.0f);
}

// ---- parallel 3-phase scan of deg -> off/cur ----
__global__ void k_scan1() {   // per-block sums, 391 x 256
    __shared__ int red[8];
    int i = blockIdx.x * 256 + threadIdx.x;
    int v = (i < NN) ? g_deg[i] : 0;
#pragma unroll
    for (int o = 16; o; o >>= 1) v += __shfl_xor_sync(0xffffffffu, v, o);
    if ((threadIdx.x & 31) == 0) red[threadIdx.x >> 5] = v;
    __syncthreads();
    if (threadIdx.x == 0) {
        int s = 0;
        for (int w = 0; w < 8; w++) s += red[w];
        g_part[blockIdx.x] = s;
    }
}
__global__ void k_scan2() {   // 1 block, 512 threads: exclusive scan of g_part
    __shared__ int sh[512];
    int t = threadIdx.x;
    sh[t] = (t < NB_SCAN) ? g_part[t] : 0;
    __syncthreads();
    for (int o = 1; o < 512; o <<= 1) {
        int v = (t >= o) ? sh[t - o] : 0;
        __syncthreads();
        sh[t] += v;
        __syncthreads();
    }
    if (t < NB_SCAN) g_part[t] = (t == 0) ? 0 : sh[t - 1];   // exclusive
    if (t == 0) g_off[NN] = sh[NB_SCAN - 1];                  // total = EE
}
__global__ void k_scan3() {   // local exclusive scan + base, 391 x 256
    __shared__ int sh[256];
    int t = threadIdx.x;
    int i = blockIdx.x * 256 + t;
    int v = (i < NN) ? g_deg[i] : 0;
    sh[t] = v;
    __syncthreads();
    for (int o = 1; o < 256; o <<= 1) {
        int u = (t >= o) ? sh[t - o] : 0;
        __syncthreads();
        sh[t] += u;
        __syncthreads();
    }
    if (i < NN) {
        int off = g_part[blockIdx.x] + sh[t] - v;   // exclusive
        g_off[i] = off;
        g_cur[i] = off;
    }
}
__global__ void k_csr_fill(const int* __restrict__ ei) {
    int e = blockIdx.x * blockDim.x + threadIdx.x;
    if (e >= EE) return;
    int is64 = g_is64;
    int src = is64 ? ei[2 * e] : ei[e];
    int dst = is64 ? ei[2 * EE + 2 * e] : ei[EE + e];
    int pos = atomicAdd(&g_cur[dst], 1);
    g_csrc[pos] = src;
    g_cw[pos] = g_dinv[src] * g_dinv[dst];
}
__global__ void k_conv_w(const float* __restrict__ W, __half* __restrict__ Th) {
    int k = blockIdx.x;
    for (int n = threadIdx.x; n < HH; n += blockDim.x)
        Th[(size_t)n * HH + k] = __float2half_rn(W[(size_t)k * HH + n]);
}

// fp32 -> fp16, optional fused BN+LReLU
__global__ void k_split(const float4* __restrict__ in,
                        const float* __restrict__ scale,
                        const float* __restrict__ shift,
                        uint2* __restrict__ outh) {
    int i = blockIdx.x * blockDim.x + threadIdx.x;
    if (i >= NN * (HH / 4)) return;
    float4 v = in[i];
    if (scale) {
        int c = (i & (HH / 4 - 1)) << 2;
        v = xform(v, c, scale, shift);
    }
    uint2 hp;
    hp.x = packh(__float2half_rn(v.x), __float2half_rn(v.y));
    hp.y = packh(__float2half_rn(v.z), __float2half_rn(v.w));
    outh[i] = hp;
}

// ---------------- GEMM: fp16 HMMA, cp.async 2-stage, fp16 output ----------
#define BM 128
#define BNT 128
#define BK 32
#define NCHUNK (HH / BK)   // 16
#define PADK 40
#define ROWB (PADK * 2)
#define OFF_A 0
#define OFF_B 10240
#define STG   20480
#define SMEMSZ (2 * STG)   // 40960

__global__ __launch_bounds__(256, 2)
void k_gemm(const __half* __restrict__ Ah,
            const __half* __restrict__ Wh,
            const float* __restrict__ bias,
            __half* __restrict__ Ch) {
    extern __shared__ char smem[];
    const uint32_t sbase = smem_u32(smem);
    const int tid = threadIdx.x;
    const int wid = tid >> 5;
    const int lane = tid & 31;
    const int bm = (blockIdx.x >> 2) * BM;
    const int bn = (blockIdx.x & 3) * BNT;
    const int wm = (wid & 1) * 64;
    const int wn = (wid >> 1) * 32;

    const char* pAh = (const char*)Ah;
    const char* pWh = (const char*)Wh;

    float acc[4][4][4];
#pragma unroll
    for (int i = 0; i < 4; i++)
#pragma unroll
        for (int j = 0; j < 4; j++)
#pragma unroll
            for (int f = 0; f < 4; f++) acc[i][j][f] = 0.f;

#define ISSUE(s)                                                              \
    do {                                                                      \
        const uint32_t stu = sbase + ((s) & 1) * STG;                         \
        const size_t kb = (size_t)(s) * 64;                                   \
        _Pragma("unroll")                                                     \
        for (int i = 0; i < 2; i++) {                                         \
            int idx = tid + i * 256;                                          \
            int r = idx >> 2, c16 = (idx & 3) << 4;                           \
            int grow = bm + r;                                                \
            if (grow < NN)                                                    \
                cp16(stu + OFF_A + r * ROWB + c16,                            \
                     pAh + (size_t)grow * (HH * 2) + kb + c16);               \
            cp16(stu + OFF_B + r * ROWB + c16,                                \
                 pWh + (size_t)(bn + r) * (HH * 2) + kb + c16);               \
        }                                                                     \
    } while (0)

    ISSUE(0);
    asm volatile("cp.async.commit_group;" ::: "memory");

    for (int s = 0; s < NCHUNK; s++) {
        if (s > 0) __syncthreads();
        if (s + 1 < NCHUNK) ISSUE(s + 1);
        asm volatile("cp.async.commit_group;" ::: "memory");
        asm volatile("cp.async.wait_group 1;" ::: "memory");
        __syncthreads();

        const uint32_t stu = sbase + (s & 1) * STG;
        const uint32_t lrow = (lane & 15);
        const uint32_t lk = (lane >> 4) * 8;
#pragma unroll
        for (int ks = 0; ks < 2; ks++) {
            const int k0 = ks * 16;
            uint32_t bh[4][2];
#pragma unroll
            for (int p = 0; p < 2; p++) {
                uint32_t off = ((wn + p * 16 + lrow) * PADK + k0 + lk) * 2;
                uint32_t t[4];
                ldsm_x4(t, stu + OFF_B + off);
                bh[p * 2 + 0][0] = t[0]; bh[p * 2 + 0][1] = t[2];
                bh[p * 2 + 1][0] = t[1]; bh[p * 2 + 1][1] = t[3];
            }
#pragma unroll
            for (int mi = 0; mi < 4; mi++) {
                uint32_t off = ((wm + mi * 16 + lrow) * PADK + k0 + lk) * 2;
                uint32_t ah[4];
                ldsm_x4(ah, stu + OFF_A + off);
#pragma unroll
                for (int ni = 0; ni < 4; ni++)
                    mma_f16(acc[mi][ni], ah, bh[ni]);
            }
        }
    }

    // ---- epilogue: fp16 output (+ optional bias) ----
#pragma unroll
    for (int mi = 0; mi < 4; mi++) {
        int row0 = bm + wm + mi * 16 + (lane >> 2);
        int row1 = row0 + 8;
#pragma unroll
        for (int ni = 0; ni < 4; ni++) {
            int col = bn + wn + ni * 8 + (lane & 3) * 2;
            float b0 = bias ? bias[col] : 0.f;
            float b1 = bias ? bias[col + 1] : 0.f;
            if (row0 < NN)
                *(uint32_t*)(Ch + (size_t)row0 * HH + col) =
                    packh(__float2half_rn(acc[mi][ni][0] + b0),
                          __float2half_rn(acc[mi][ni][1] + b1));
            if (row1 < NN)
                *(uint32_t*)(Ch + (size_t)row1 * HH + col) =
                    packh(__float2half_rn(acc[mi][ni][2] + b0),
                          __float2half_rn(acc[mi][ni][3] + b1));
        }
    }
}

// ---------------- gather aggregation + fused BN stats ----------------------
// C[i] = bc + dinv[i]^2*B[i] + sum_e w_e*B[src_e]; one warp per node.
// Also accumulates colsum/colsq (per-block smem reduce -> global atomics).
// Grid is exactly NN*32/256 = 12500 blocks: every warp has a valid node.
__global__ __launch_bounds__(256)
void k_gather(const __half* __restrict__ B, const float* __restrict__ bc,
              float* __restrict__ C) {
    __shared__ float ssum[HH];
    __shared__ float ssq[HH];
    for (int i = threadIdx.x; i < HH; i += 256) {
        ssum[i] = 0.f;
        ssq[i] = 0.f;
    }
    __syncthreads();

    int node = (blockIdx.x * blockDim.x + threadIdx.x) >> 5;
    int lane = threadIdx.x & 31;
    const int col = lane * 16;

    float acc[16];
    const float4* bc4 = (const float4*)(bc + col);
#pragma unroll
    for (int j = 0; j < 4; j++) {
        float4 b = __ldg(bc4 + j);
        acc[4 * j + 0] = b.x;
        acc[4 * j + 1] = b.y;
        acc[4 * j + 2] = b.z;
        acc[4 * j + 3] = b.w;
    }

    float dw = g_dinv[node];
    dw *= dw;
    accum16(acc, (const uint4*)(B + (size_t)node * HH + col), dw);

    int k0 = g_off[node], k1 = g_off[node + 1];
    for (int k = k0; k < k1; k++) {
        int src = g_csrc[k];
        float w = g_cw[k];
        accum16(acc, (const uint4*)(B + (size_t)src * HH + col), w);
    }

    float4* o = (float4*)(C + (size_t)node * HH + col);
#pragma unroll
    for (int j = 0; j < 4; j++)
        o[j] = make_float4(acc[4 * j], acc[4 * j + 1], acc[4 * j + 2],
                           acc[4 * j + 3]);

    // fused BN stats: lanes of different warps share addresses (8-way max)
#pragma unroll
    for (int j = 0; j < 16; j++) {
        atomicAdd(&ssum[col + j], acc[j]);
        atomicAdd(&ssq[col + j], acc[j] * acc[j]);
    }
    __syncthreads();
    for (int i = threadIdx.x; i < HH; i += 256) {
        atomicAdd(&g_colsum[i], ssum[i]);
        atomicAdd(&g_colsq[i], ssq[i]);
    }
}

// ---------------- batchnorm finalize ----------------
__global__ void k_bnzero() {
    int i = threadIdx.x;
    g_colsum[i] = 0.f;
    g_colsq[i] = 0.f;
}
__global__ void k_bn_final(const float* __restrict__ gamma,
                           const float* __restrict__ beta) {
    int c = threadIdx.x;
    float inv_n = 1.0f / (float)NN;
    float mean = g_colsum[c] * inv_n;
    float var = g_colsq[c] * inv_n - mean * mean;
    float sc = gamma[c] * rsqrtf(var + BN_EPS);
    g_scale[c] = sc;
    g_shift[c] = beta[c] - mean * sc;
}

// ---------------- fused tail ----------------
__global__ void k_weff(const float* __restrict__ W2, const float* __restrict__ b2,
                       const float* __restrict__ WO, const float* __restrict__ bO) {
    int b = blockIdx.x;
    const float* rowp = (b < HH) ? (W2 + (size_t)b * HH) : b2;
    float s = 0.f;
    for (int j = threadIdx.x; j < HH; j += 256) s += rowp[j] * WO[j];
#pragma unroll
    for (int o = 16; o; o >>= 1) s += __shfl_xor_sync(0xffffffffu, s, o);
    __shared__ float red[8];
    if ((threadIdx.x & 31) == 0) red[threadIdx.x >> 5] = s;
    __syncthreads();
    if (threadIdx.x == 0) {
        float t = 0.f;
        for (int i = 0; i < 8; i++) t += red[i];
        g_weff[b] = (b < HH) ? t : (t + bO[0]);
    }
}

__global__ void k_out(const float* __restrict__ A, float* __restrict__ out) {
    int w = (blockIdx.x * blockDim.x + threadIdx.x) >> 5;
    int lane = threadIdx.x & 31;
    if (w >= NN) return;
    const float4* row = (const float4*)(A + (size_t)w * HH);
    const float4* wf = (const float4*)g_weff;
    const float4* sc4 = (const float4*)g_scale;
    const float4* sh4 = (const float4*)g_shift;
    float s = 0.f;
#pragma unroll
    for (int i = 0; i < 4; i++) {
        int idx = lane + 32 * i;
        float4 a = row[idx];
        float4 b = wf[idx];
        float4 sc = sc4[idx];
        float4 sh = sh4[idx];
        a.x = lrelu1(fmaf(sc.x, a.x, sh.x));
        a.y = lrelu1(fmaf(sc.y, a.y, sh.y));
        a.z = lrelu1(fmaf(sc.z, a.z, sh.z));
        a.w = lrelu1(fmaf(sc.w, a.w, sh.w));
        s += a.x * b.x + a.y * b.y + a.z * b.z + a.w * b.w;
    }
#pragma unroll
    for (int o = 16; o; o >>= 1) s += __shfl_xor_sync(0xffffffffu, s, o);
    if (lane == 0) {
        float t = s + g_weff[HH];
        out[w] = 1.0f / (1.0f + expf(-t));
    }
}

// ---------------- launcher ----------------
extern "C" void kernel_launch(void* const* d_in, const int* in_sizes, int n_in,
                              void* d_out, int out_size) {
    const float* x     = (const float*)d_in[0];
    const int*   ei    = (const int*)d_in[1];
    const float* W1    = (const float*)d_in[2];
    const float* b1    = (const float*)d_in[3];
    const float* Wc    = (const float*)d_in[4];
    const float* bc    = (const float*)d_in[5];
    const float* gamma = (const float*)d_in[6];
    const float* beta  = (const float*)d_in[7];
    const float* W2    = (const float*)d_in[8];
    const float* b2    = (const float*)d_in[9];
    const float* WO    = (const float*)d_in[10];
    const float* bO    = (const float*)d_in[11];
    float* out = (float*)d_out;

    float *pC, *pScale, *pShift;
    cudaGetSymbolAddress((void**)&pC, g_C);
    cudaGetSymbolAddress((void**)&pScale, g_scale);
    cudaGetSymbolAddress((void**)&pShift, g_shift);
    __half *pAh, *pB16, *w1h, *wch;
    cudaGetSymbolAddress((void**)&pAh, g_Ah);
    cudaGetSymbolAddress((void**)&pB16, g_B16);
    cudaGetSymbolAddress((void**)&w1h, g_w1h);
    cudaGetSymbolAddress((void**)&wch, g_wch);

    cudaFuncSetAttribute(k_gemm, cudaFuncAttributeMaxDynamicSharedMemorySize,
                         SMEMSZ);

    k_prep<<<(NN + 255) / 256, 256>>>(ei);
    k_deg<<<(EE + 255) / 256, 256>>>(ei);
    k_dinv<<<(NN + 255) / 256, 256>>>();
    k_scan1<<<NB_SCAN, 256>>>();
    k_scan2<<<1, 512>>>();
    k_scan3<<<NB_SCAN, 256>>>();
    k_csr_fill<<<(EE + 255) / 256, 256>>>(ei);
    k_conv_w<<<HH, 256>>>(W1, w1h);
    k_conv_w<<<HH, 256>>>(Wc, wch);
    k_weff<<<HH + 1, 256>>>(W2, b2, WO, bO);

    const int nblk = ((NN + BM - 1) / BM) * 4;   // 3128
    const int elem4 = NN * (HH / 4);
    const int gthr = (NN * 32) / 256;            // 12500, exact

    // x -> fp16
    k_split<<<(elem4 + 255) / 256, 256>>>((const float4*)x, nullptr, nullptr,
                                          (uint2*)pAh);

    // GEMM1: h = x@W1 + b1 (fp16 out)
    k_gemm<<<nblk, 256, SMEMSZ>>>(pAh, w1h, b1, pB16);
    {
        __half* t = pAh; pAh = pB16; pB16 = t;
    }

    // layer 0: B16 = h@Wc (fp16); gather (+stats) -> C; finalize BN
    k_gemm<<<nblk, 256, SMEMSZ>>>(pAh, wch, nullptr, pB16);
    k_bnzero<<<1, 512>>>();
    k_gather<<<gthr, 256>>>(pB16, bc, pC);
    k_bn_final<<<1, 512>>>(gamma, beta);

    // C -> fp16 with fused BN+LReLU
    k_split<<<(elem4 + 255) / 256, 256>>>((const float4*)pC, pScale, pShift,
                                          (uint2*)pAh);

    // layer 1
    k_gemm<<<nblk, 256, SMEMSZ>>>(pAh, wch, nullptr, pB16);
    k_bnzero<<<1, 512>>>();
    k_gather<<<gthr, 256>>>(pB16, bc, pC);
    k_bn_final<<<1, 512>>>(gamma, beta);

    // fused tail
    k_out<<<(NN * 32 + 255) / 256, 256>>>(pC, out);
}

// round 13
// speedup vs baseline: 1.8809x; 1.8809x over previous
#include <cuda_runtime.h>
#include <cuda_fp16.h>
#include <cstdint>
#include <cstddef>

#define NN 100000
#define HH 512
#define EE 160000
#define BN_EPS 1e-5f
#define SLOPE 0.01f
#define NB_SCAN 391          // ceil(NN/256)

// ---------------- scratch ----------------
__device__ float  g_C[(size_t)NN * HH];     // fp32 node state (agg output)
__device__ __half g_Ah[(size_t)NN * HH];    // fp16 GEMM input
__device__ __half g_B16[(size_t)NN * HH];   // fp16 GEMM output (feeds gather)
__device__ float g_dinv[NN];
__device__ int   g_deg[NN];
__device__ int   g_off[NN + 1];
__device__ int   g_cur[NN];
__device__ int   g_part[NB_SCAN];
__device__ int   g_csrc[EE];
__device__ float g_cw[EE];
__device__ float g_colsum[HH];
__device__ float g_colsq[HH];
__device__ float g_scale[HH];
__device__ float g_shift[HH];
__device__ float g_weff[HH + 1];
__device__ int   g_is64;

// transposed fp16 weights: T[n][k] = fp16(W[k][n])
__device__ __half g_w1h[HH * HH];
__device__ __half g_wch[HH * HH];

// ---------------- helpers ----------------
__device__ __forceinline__ uint32_t smem_u32(const void* p) {
    uint32_t a;
    asm("{ .reg .u64 t; cvta.to.shared.u64 t, %1; cvt.u32.u64 %0, t; }"
        : "=r"(a) : "l"(p));
    return a;
}
__device__ __forceinline__ void ldsm_x4(uint32_t* r, uint32_t addr) {
    asm volatile("ldmatrix.sync.aligned.m8n8.x4.shared.b16 {%0,%1,%2,%3}, [%4];"
                 : "=r"(r[0]), "=r"(r[1]), "=r"(r[2]), "=r"(r[3]) : "r"(addr));
}
__device__ __forceinline__ void mma_f16(float* d, const uint32_t* a,
                                        const uint32_t* b) {
    asm volatile(
        "mma.sync.aligned.m16n8k16.row.col.f32.f16.f16.f32 "
        "{%0,%1,%2,%3}, {%4,%5,%6,%7}, {%8,%9}, {%0,%1,%2,%3};"
        : "+f"(d[0]), "+f"(d[1]), "+f"(d[2]), "+f"(d[3])
        : "r"(a[0]), "r"(a[1]), "r"(a[2]), "r"(a[3]), "r"(b[0]), "r"(b[1]));
}
__device__ __forceinline__ void cp16(uint32_t dst, const void* src) {
    asm volatile("cp.async.cg.shared.global [%0], [%1], 16;"
                 :: "r"(dst), "l"(src));
}
__device__ __forceinline__ float lrelu1(float x) {
    return x >= 0.f ? x : SLOPE * x;
}
__device__ __forceinline__ float4 xform(float4 v, int col,
                                        const float* __restrict__ scale,
                                        const float* __restrict__ shift) {
    float4 s = __ldg((const float4*)(scale + col));
    float4 t = __ldg((const float4*)(shift + col));
    v.x = lrelu1(fmaf(s.x, v.x, t.x));
    v.y = lrelu1(fmaf(s.y, v.y, t.y));
    v.z = lrelu1(fmaf(s.z, v.z, t.z));
    v.w = lrelu1(fmaf(s.w, v.w, t.w));
    return v;
}
__device__ __forceinline__ uint32_t packh(__half a, __half b) {
    return ((uint32_t)__half_as_ushort(a)) |
           ((uint32_t)__half_as_ushort(b) << 16);
}
// accumulate 16 halves (2x uint4) scaled by w into acc[16]
__device__ __forceinline__ void accum16(float* acc, const uint4* p, float w) {
    uint4 u0 = __ldg(p), u1 = __ldg(p + 1);
    uint32_t ua[8] = {u0.x, u0.y, u0.z, u0.w, u1.x, u1.y, u1.z, u1.w};
#pragma unroll
    for (int j = 0; j < 8; j++) {
        float2 f = __half22float2(*(__half2*)&ua[j]);
        acc[2 * j + 0] = fmaf(w, f.x, acc[2 * j + 0]);
        acc[2 * j + 1] = fmaf(w, f.y, acc[2 * j + 1]);
    }
}

// ---------------- setup ----------------
__global__ void k_prep(const int* __restrict__ ei) {
    int i = blockIdx.x * blockDim.x + threadIdx.x;
    if (i == 0)
        g_is64 = ((ei[1] | ei[3] | ei[5] | ei[7] | ei[9]) == 0) ? 1 : 0;
    if (i < NN) g_deg[i] = 0;
}
__global__ void k_deg(const int* __restrict__ ei) {
    int e = blockIdx.x * blockDim.x + threadIdx.x;
    if (e >= EE) return;
    int is64 = g_is64;
    int dst = is64 ? ei[2 * EE + 2 * e] : ei[EE + e];
    atomicAdd(&g_deg[dst], 1);
}
__global__ void k_dinv() {
    int i = blockIdx.x * blockDim.x + threadIdx.x;
    if (i < NN) g_dinv[i] = rsqrtf((float)g_deg[i] + 1.0f);
}

// ---- parallel 3-phase scan of deg -> off/cur ----
__global__ void k_scan1() {   // per-block sums, 391 x 256
    __shared__ int red[8];
    int i = blockIdx.x * 256 + threadIdx.x;
    int v = (i < NN) ? g_deg[i] : 0;
#pragma unroll
    for (int o = 16; o; o >>= 1) v += __shfl_xor_sync(0xffffffffu, v, o);
    if ((threadIdx.x & 31) == 0) red[threadIdx.x >> 5] = v;
    __syncthreads();
    if (threadIdx.x == 0) {
        int s = 0;
        for (int w = 0; w < 8; w++) s += red[w];
        g_part[blockIdx.x] = s;
    }
}
__global__ void k_scan2() {   // 1 block, 512 threads: exclusive scan of g_part
    __shared__ int sh[512];
    int t = threadIdx.x;
    sh[t] = (t < NB_SCAN) ? g_part[t] : 0;
    __syncthreads();
    for (int o = 1; o < 512; o <<= 1) {
        int v = (t >= o) ? sh[t - o] : 0;
        __syncthreads();
        sh[t] += v;
        __syncthreads();
    }
    if (t < NB_SCAN) g_part[t] = (t == 0) ? 0 : sh[t - 1];   // exclusive
    if (t == 0) g_off[NN] = sh[NB_SCAN - 1];                  // total = EE
}
__global__ void k_scan3() {   // local exclusive scan + base, 391 x 256
    __shared__ int sh[256];
    int t = threadIdx.x;
    int i = blockIdx.x * 256 + t;
    int v = (i < NN) ? g_deg[i] : 0;
    sh[t] = v;
    __syncthreads();
    for (int o = 1; o < 256; o <<= 1) {
        int u = (t >= o) ? sh[t - o] : 0;
        __syncthreads();
        sh[t] += u;
        __syncthreads();
    }
    if (i < NN) {
        int off = g_part[blockIdx.x] + sh[t] - v;   // exclusive
        g_off[i] = off;
        g_cur[i] = off;
    }
}
__global__ void k_csr_fill(const int* __restrict__ ei) {
    int e = blockIdx.x * blockDim.x + threadIdx.x;
    if (e >= EE) return;
    int is64 = g_is64;
    int src = is64 ? ei[2 * e] : ei[e];
    int dst = is64 ? ei[2 * EE + 2 * e] : ei[EE + e];
    int pos = atomicAdd(&g_cur[dst], 1);
    g_csrc[pos] = src;
    g_cw[pos] = g_dinv[src] * g_dinv[dst];
}
__global__ void k_conv_w(const float* __restrict__ W, __half* __restrict__ Th) {
    int k = blockIdx.x;
    for (int n = threadIdx.x; n < HH; n += blockDim.x)
        Th[(size_t)n * HH + k] = __float2half_rn(W[(size_t)k * HH + n]);
}

// fp32 -> fp16, optional fused BN+LReLU
__global__ void k_split(const float4* __restrict__ in,
                        const float* __restrict__ scale,
                        const float* __restrict__ shift,
                        uint2* __restrict__ outh) {
    int i = blockIdx.x * blockDim.x + threadIdx.x;
    if (i >= NN * (HH / 4)) return;
    float4 v = in[i];
    if (scale) {
        int c = (i & (HH / 4 - 1)) << 2;
        v = xform(v, c, scale, shift);
    }
    uint2 hp;
    hp.x = packh(__float2half_rn(v.x), __float2half_rn(v.y));
    hp.y = packh(__float2half_rn(v.z), __float2half_rn(v.w));
    outh[i] = hp;
}

// ---------------- GEMM: fp16 HMMA, cp.async 2-stage, fp16 output ----------
#define BM 128
#define BNT 128
#define BK 32
#define NCHUNK (HH / BK)   // 16
#define PADK 40
#define ROWB (PADK * 2)
#define OFF_A 0
#define OFF_B 10240
#define STG   20480
#define SMEMSZ (2 * STG)   // 40960

__global__ __launch_bounds__(256, 2)
void k_gemm(const __half* __restrict__ Ah,
            const __half* __restrict__ Wh,
            const float* __restrict__ bias,
            __half* __restrict__ Ch) {
    extern __shared__ char smem[];
    const uint32_t sbase = smem_u32(smem);
    const int tid = threadIdx.x;
    const int wid = tid >> 5;
    const int lane = tid & 31;
    const int bm = (blockIdx.x >> 2) * BM;
    const int bn = (blockIdx.x & 3) * BNT;
    const int wm = (wid & 1) * 64;
    const int wn = (wid >> 1) * 32;

    const char* pAh = (const char*)Ah;
    const char* pWh = (const char*)Wh;

    float acc[4][4][4];
#pragma unroll
    for (int i = 0; i < 4; i++)
#pragma unroll
        for (int j = 0; j < 4; j++)
#pragma unroll
            for (int f = 0; f < 4; f++) acc[i][j][f] = 0.f;

#define ISSUE(s)                                                              \
    do {                                                                      \
        const uint32_t stu = sbase + ((s) & 1) * STG;                         \
        const size_t kb = (size_t)(s) * 64;                                   \
        _Pragma("unroll")                                                     \
        for (int i = 0; i < 2; i++) {                                         \
            int idx = tid + i * 256;                                          \
            int r = idx >> 2, c16 = (idx & 3) << 4;                           \
            int grow = bm + r;                                                \
            if (grow < NN)                                                    \
                cp16(stu + OFF_A + r * ROWB + c16,                            \
                     pAh + (size_t)grow * (HH * 2) + kb + c16);               \
            cp16(stu + OFF_B + r * ROWB + c16,                                \
                 pWh + (size_t)(bn + r) * (HH * 2) + kb + c16);               \
        }                                                                     \
    } while (0)

    ISSUE(0);
    asm volatile("cp.async.commit_group;" ::: "memory");

    for (int s = 0; s < NCHUNK; s++) {
        if (s > 0) __syncthreads();
        if (s + 1 < NCHUNK) ISSUE(s + 1);
        asm volatile("cp.async.commit_group;" ::: "memory");
        asm volatile("cp.async.wait_group 1;" ::: "memory");
        __syncthreads();

        const uint32_t stu = sbase + (s & 1) * STG;
        const uint32_t lrow = (lane & 15);
        const uint32_t lk = (lane >> 4) * 8;
#pragma unroll
        for (int ks = 0; ks < 2; ks++) {
            const int k0 = ks * 16;
            uint32_t bh[4][2];
#pragma unroll
            for (int p = 0; p < 2; p++) {
                uint32_t off = ((wn + p * 16 + lrow) * PADK + k0 + lk) * 2;
                uint32_t t[4];
                ldsm_x4(t, stu + OFF_B + off);
                bh[p * 2 + 0][0] = t[0]; bh[p * 2 + 0][1] = t[2];
                bh[p * 2 + 1][0] = t[1]; bh[p * 2 + 1][1] = t[3];
            }
#pragma unroll
            for (int mi = 0; mi < 4; mi++) {
                uint32_t off = ((wm + mi * 16 + lrow) * PADK + k0 + lk) * 2;
                uint32_t ah[4];
                ldsm_x4(ah, stu + OFF_A + off);
#pragma unroll
                for (int ni = 0; ni < 4; ni++)
                    mma_f16(acc[mi][ni], ah, bh[ni]);
            }
        }
    }

    // ---- epilogue: fp16 output (+ optional bias) ----
#pragma unroll
    for (int mi = 0; mi < 4; mi++) {
        int row0 = bm + wm + mi * 16 + (lane >> 2);
        int row1 = row0 + 8;
#pragma unroll
        for (int ni = 0; ni < 4; ni++) {
            int col = bn + wn + ni * 8 + (lane & 3) * 2;
            float b0 = bias ? bias[col] : 0.f;
            float b1 = bias ? bias[col + 1] : 0.f;
            if (row0 < NN)
                *(uint32_t*)(Ch + (size_t)row0 * HH + col) =
                    packh(__float2half_rn(acc[mi][ni][0] + b0),
                          __float2half_rn(acc[mi][ni][1] + b1));
            if (row1 < NN)
                *(uint32_t*)(Ch + (size_t)row1 * HH + col) =
                    packh(__float2half_rn(acc[mi][ni][2] + b0),
                          __float2half_rn(acc[mi][ni][3] + b1));
        }
    }
}

// ---------------- gather aggregation (CSR, no atomics, no fused stats) -----
// C[i] = bc + dinv[i]^2 * B[i] + sum_e w_e * B[src_e]; one warp per node.
__global__ __launch_bounds__(256)
void k_gather(const __half* __restrict__ B, const float* __restrict__ bc,
              float* __restrict__ C) {
    int node = (blockIdx.x * blockDim.x + threadIdx.x) >> 5;
    int lane = threadIdx.x & 31;
    if (node >= NN) return;
    const int col = lane * 16;

    float acc[16];
    const float4* bc4 = (const float4*)(bc + col);
#pragma unroll
    for (int j = 0; j < 4; j++) {
        float4 b = __ldg(bc4 + j);
        acc[4 * j + 0] = b.x;
        acc[4 * j + 1] = b.y;
        acc[4 * j + 2] = b.z;
        acc[4 * j + 3] = b.w;
    }

    float dw = g_dinv[node];
    dw *= dw;
    accum16(acc, (const uint4*)(B + (size_t)node * HH + col), dw);

    int k0 = g_off[node], k1 = g_off[node + 1];
    for (int k = k0; k < k1; k++) {
        int src = g_csrc[k];
        float w = g_cw[k];
        accum16(acc, (const uint4*)(B + (size_t)src * HH + col), w);
    }

    float4* o = (float4*)(C + (size_t)node * HH + col);
#pragma unroll
    for (int j = 0; j < 4; j++)
        o[j] = make_float4(acc[4 * j], acc[4 * j + 1], acc[4 * j + 2],
                           acc[4 * j + 3]);
}

// ---------------- batchnorm ----------------
__global__ void k_bnzero() {
    int i = threadIdx.x;
    g_colsum[i] = 0.f;
    g_colsq[i] = 0.f;
}
__global__ void k_bn_stats(const float* __restrict__ A) {
    int c = threadIdx.x;
    float s0 = 0.f, q0 = 0.f, s1 = 0.f, q1 = 0.f;
    for (int r = blockIdx.x; r < NN; r += gridDim.x) {
        const float* row = A + (size_t)r * HH;
        float v0 = row[c];
        float v1 = row[c + 256];
        s0 += v0; q0 += v0 * v0;
        s1 += v1; q1 += v1 * v1;
    }
    atomicAdd(&g_colsum[c], s0);
    atomicAdd(&g_colsq[c], q0);
    atomicAdd(&g_colsum[c + 256], s1);
    atomicAdd(&g_colsq[c + 256], q1);
}
__global__ void k_bn_final(const float* __restrict__ gamma,
                           const float* __restrict__ beta) {
    int c = threadIdx.x;
    float inv_n = 1.0f / (float)NN;
    float mean = g_colsum[c] * inv_n;
    float var = g_colsq[c] * inv_n - mean * mean;
    float sc = gamma[c] * rsqrtf(var + BN_EPS);
    g_scale[c] = sc;
    g_shift[c] = beta[c] - mean * sc;
}

// ---------------- fused tail ----------------
__global__ void k_weff(const float* __restrict__ W2, const float* __restrict__ b2,
                       const float* __restrict__ WO, const float* __restrict__ bO) {
    int b = blockIdx.x;
    const float* rowp = (b < HH) ? (W2 + (size_t)b * HH) : b2;
    float s = 0.f;
    for (int j = threadIdx.x; j < HH; j += 256) s += rowp[j] * WO[j];
#pragma unroll
    for (int o = 16; o; o >>= 1) s += __shfl_xor_sync(0xffffffffu, s, o);
    __shared__ float red[8];
    if ((threadIdx.x & 31) == 0) red[threadIdx.x >> 5] = s;
    __syncthreads();
    if (threadIdx.x == 0) {
        float t = 0.f;
        for (int i = 0; i < 8; i++) t += red[i];
        g_weff[b] = (b < HH) ? t : (t + bO[0]);
    }
}

__global__ void k_out(const float* __restrict__ A, float* __restrict__ out) {
    int w = (blockIdx.x * blockDim.x + threadIdx.x) >> 5;
    int lane = threadIdx.x & 31;
    if (w >= NN) return;
    const float4* row = (const float4*)(A + (size_t)w * HH);
    const float4* wf = (const float4*)g_weff;
    const float4* sc4 = (const float4*)g_scale;
    const float4* sh4 = (const float4*)g_shift;
    float s = 0.f;
#pragma unroll
    for (int i = 0; i < 4; i++) {
        int idx = lane + 32 * i;
        float4 a = row[idx];
        float4 b = wf[idx];
        float4 sc = sc4[idx];
        float4 sh = sh4[idx];
        a.x = lrelu1(fmaf(sc.x, a.x, sh.x));
        a.y = lrelu1(fmaf(sc.y, a.y, sh.y));
        a.z = lrelu1(fmaf(sc.z, a.z, sh.z));
        a.w = lrelu1(fmaf(sc.w, a.w, sh.w));
        s += a.x * b.x + a.y * b.y + a.z * b.z + a.w * b.w;
    }
#pragma unroll
    for (int o = 16; o; o >>= 1) s += __shfl_xor_sync(0xffffffffu, s, o);
    if (lane == 0) {
        float t = s + g_weff[HH];
        out[w] = 1.0f / (1.0f + expf(-t));
    }
}

// ---------------- launcher ----------------
extern "C" void kernel_launch(void* const* d_in, const int* in_sizes, int n_in,
                              void* d_out, int out_size) {
    const float* x     = (const float*)d_in[0];
    const int*   ei    = (const int*)d_in[1];
    const float* W1    = (const float*)d_in[2];
    const float* b1    = (const float*)d_in[3];
    const float* Wc    = (const float*)d_in[4];
    const float* bc    = (const float*)d_in[5];
    const float* gamma = (const float*)d_in[6];
    const float* beta  = (const float*)d_in[7];
    const float* W2    = (const float*)d_in[8];
    const float* b2    = (const float*)d_in[9];
    const float* WO    = (const float*)d_in[10];
    const float* bO    = (const float*)d_in[11];
    float* out = (float*)d_out;

    float *pC, *pScale, *pShift;
    cudaGetSymbolAddress((void**)&pC, g_C);
    cudaGetSymbolAddress((void**)&pScale, g_scale);
    cudaGetSymbolAddress((void**)&pShift, g_shift);
    __half *pAh, *pB16, *w1h, *wch;
    cudaGetSymbolAddress((void**)&pAh, g_Ah);
    cudaGetSymbolAddress((void**)&pB16, g_B16);
    cudaGetSymbolAddress((void**)&w1h, g_w1h);
    cudaGetSymbolAddress((void**)&wch, g_wch);

    cudaFuncSetAttribute(k_gemm, cudaFuncAttributeMaxDynamicSharedMemorySize,
                         SMEMSZ);

    k_prep<<<(NN + 255) / 256, 256>>>(ei);
    k_deg<<<(EE + 255) / 256, 256>>>(ei);
    k_dinv<<<(NN + 255) / 256, 256>>>();
    k_scan1<<<NB_SCAN, 256>>>();
    k_scan2<<<1, 512>>>();
    k_scan3<<<NB_SCAN, 256>>>();
    k_csr_fill<<<(EE + 255) / 256, 256>>>(ei);
    k_conv_w<<<HH, 256>>>(W1, w1h);
    k_conv_w<<<HH, 256>>>(Wc, wch);
    k_weff<<<HH + 1, 256>>>(W2, b2, WO, bO);

    const int nblk = ((NN + BM - 1) / BM) * 4;   // 3128
    const int elem4 = NN * (HH / 4);
    const int gthr = (NN * 32 + 255) / 256;      // warp per node

    // x -> fp16
    k_split<<<(elem4 + 255) / 256, 256>>>((const float4*)x, nullptr, nullptr,
                                          (uint2*)pAh);

    // GEMM1: h = x@W1 + b1 (fp16 out)
    k_gemm<<<nblk, 256, SMEMSZ>>>(pAh, w1h, b1, pB16);
    {
        __half* t = pAh; pAh = pB16; pB16 = t;
    }

    // layer 0: B16 = h@Wc (fp16); gather -> C; stats
    k_gemm<<<nblk, 256, SMEMSZ>>>(pAh, wch, nullptr, pB16);
    k_gather<<<gthr, 256>>>(pB16, bc, pC);
    k_bnzero<<<1, 512>>>();
    k_bn_stats<<<2048, 256>>>(pC);
    k_bn_final<<<1, 512>>>(gamma, beta);

    // C -> fp16 with fused BN+LReLU
    k_split<<<(elem4 + 255) / 256, 256>>>((const float4*)pC, pScale, pShift,
                                          (uint2*)pAh);

    // layer 1
    k_gemm<<<nblk, 256, SMEMSZ>>>(pAh, wch, nullptr, pB16);
    k_gather<<<gthr, 256>>>(pB16, bc, pC);
    k_bnzero<<<1, 512>>>();
    k_bn_stats<<<2048, 256>>>(pC);
    k_bn_final<<<1, 512>>>(gamma, beta);

    // fused tail
    k_out<<<(NN * 32 + 255) / 256, 256>>>(pC, out);
}